// round 17
// baseline (speedup 1.0000x reference)
#include <cuda_runtime.h>
#include <cstdint>

#define NN 50000
#define DD 64
#define EE 800000
#define SCAN_BS 1024
#define NBLK ((NN + SCAN_BS - 1) / SCAN_BS)   // 49

// Scratch (no cudaMalloc allowed)
__device__ float g_AGG[NN * DD];
__device__ float g_H[NN * DD];
__device__ int   g_counts[NN];       // zero-init at load; reset by scan each run
__device__ int   g_cursor[NN];
__device__ int2  g_ofscnt[NN];       // (offset, count) packed for gather
__device__ int   g_aggs[64];         // decoupled-lookback block aggregates
__device__ int   g_flags[64];        // zero-init; reset by fill each run
__device__ int2  g_recs[EE];         // (src, bitcast(weight)) binned by dst

// ---------------------------------------------------------------------------
// edge_index dtype is ambiguous (jnp.int64 without x64 -> int32); detect at
// runtime: int64 values < 50000 have all-zero odd 32-bit words.
// ---------------------------------------------------------------------------
__device__ __forceinline__ bool detect_i64(const int* __restrict__ ei32) {
    return (ei32[1] | ei32[3] | ei32[5] | ei32[7] |
            ei32[9] | ei32[11] | ei32[13] | ei32[15]) == 0;
}

// tf32 helpers
__device__ __forceinline__ unsigned tf32_hi(float f) {
    unsigned u;
    asm("cvt.rna.tf32.f32 %0, %1;" : "=r"(u) : "f"(f));
    return u;
}
__device__ __forceinline__ void tf32_split(float f, unsigned& hi, unsigned& lo) {
    hi = tf32_hi(f);
    lo = tf32_hi(f - __uint_as_float(hi));
}
__device__ __forceinline__ void mma8(float* c, const unsigned* a,
                                     unsigned b0, unsigned b1) {
    asm("mma.sync.aligned.m16n8k8.row.col.f32.tf32.tf32.f32 "
        "{%0,%1,%2,%3},{%4,%5,%6,%7},{%8,%9},{%0,%1,%2,%3};"
        : "+f"(c[0]), "+f"(c[1]), "+f"(c[2]), "+f"(c[3])
        : "r"(a[0]), "r"(a[1]), "r"(a[2]), "r"(a[3]), "r"(b0), "r"(b1));
}

// ---------------------------------------------------------------------------
// Histogram: 4 edges per thread for atomic MLP (latency-bound kernel).
// ---------------------------------------------------------------------------
__global__ __launch_bounds__(256) void hist_kernel(const int* __restrict__ ei32) {
    int t = blockIdx.x * blockDim.x + threadIdx.x;
    if (t >= EE / 4) return;
    bool is64 = detect_i64(ei32);
    int d0, d1, d2, d3;
    if (is64) {
        const longlong2* p = (const longlong2*)(ei32 + 2 * EE);
        longlong2 va = p[2 * t];
        longlong2 vb = p[2 * t + 1];
        d0 = (int)va.x; d1 = (int)va.y; d2 = (int)vb.x; d3 = (int)vb.y;
    } else {
        const int4* p = (const int4*)(ei32 + EE);
        int4 v = p[t];
        d0 = v.x; d1 = v.y; d2 = v.z; d3 = v.w;
    }
    atomicAdd(&g_counts[d0], 1);
    atomicAdd(&g_counts[d1], 1);
    atomicAdd(&g_counts[d2], 1);
    atomicAdd(&g_counts[d3], 1);
}

// ---------------------------------------------------------------------------
// Fused exclusive scan of g_counts (decoupled lookback, 49 blocks x 1024).
// All 49 blocks are co-resident (148 SMs) -> polling cannot deadlock.
// Writes (offset,count) to g_ofscnt, initializes g_cursor, resets g_counts.
// g_flags are zero on entry (load-init / reset by fill_kernel last replay).
// ---------------------------------------------------------------------------
__global__ __launch_bounds__(SCAN_BS) void scan_kernel() {
    __shared__ int s_wsum[32];
    __shared__ int s_prefix;

    int t = threadIdx.x;
    int b = blockIdx.x;
    int lane = t & 31;
    int w = t >> 5;
    int i = b * SCAN_BS + t;

    int v = (i < NN) ? g_counts[i] : 0;

    // warp inclusive scan
    int incl = v;
#pragma unroll
    for (int off = 1; off < 32; off <<= 1) {
        int y = __shfl_up_sync(0xffffffffu, incl, off);
        if (lane >= off) incl += y;
    }
    if (lane == 31) s_wsum[w] = incl;
    __syncthreads();

    // warp 0 scans the 32 warp sums (exclusive) + publishes block aggregate
    if (w == 0) {
        int ws = s_wsum[lane];
        int wincl = ws;
#pragma unroll
        for (int off = 1; off < 32; off <<= 1) {
            int y = __shfl_up_sync(0xffffffffu, wincl, off);
            if (lane >= off) wincl += y;
        }
        s_wsum[lane] = wincl - ws;      // exclusive warp prefix
        int total = __shfl_sync(0xffffffffu, wincl, 31);
        if (lane == 0) {
            g_aggs[b] = total;
            __threadfence();
            atomicExch(&g_flags[b], 1);
        }
        // decoupled lookback: sum aggregates of all predecessor blocks
        int pre = 0;
        if (b > 0) {
            while (true) {
                int f0 = (lane < b) ? atomicAdd(&g_flags[lane], 0) : 1;
                int f1 = (lane + 32 < b) ? atomicAdd(&g_flags[lane + 32], 0) : 1;
                if (__all_sync(0xffffffffu, f0 && f1)) break;
            }
            __threadfence();
            int a = (lane < b ? g_aggs[lane] : 0)
                  + (lane + 32 < b ? g_aggs[lane + 32] : 0);
#pragma unroll
            for (int off = 16; off > 0; off >>= 1)
                a += __shfl_xor_sync(0xffffffffu, a, off);
            pre = a;
        }
        if (lane == 0) s_prefix = pre;
    }
    __syncthreads();

    if (i < NN) {
        int o = (incl - v) + s_wsum[w] + s_prefix;
        g_ofscnt[i] = make_int2(o, v);
        g_cursor[i] = o;
        g_counts[i] = 0;                // reset for next replay
    }
}

// ---------------------------------------------------------------------------
// Fill: 4 edges per thread (atomic-return chains overlap). Also resets the
// lookback flags for the next replay (runs strictly after scan_kernel).
// ---------------------------------------------------------------------------
__global__ __launch_bounds__(256) void fill_kernel(const int* __restrict__ ei32,
                                                   const float* __restrict__ ew) {
    if (blockIdx.x == 0 && threadIdx.x < 64) g_flags[threadIdx.x] = 0;
    int t = blockIdx.x * blockDim.x + threadIdx.x;
    if (t >= EE / 4) return;
    bool is64 = detect_i64(ei32);
    int s0, s1, s2, s3, d0, d1, d2, d3;
    if (is64) {
        const longlong2* ps = (const longlong2*)ei32;
        const longlong2* pd = (const longlong2*)(ei32 + 2 * EE);
        longlong2 va = ps[2 * t], vb = ps[2 * t + 1];
        longlong2 vc = pd[2 * t], vd = pd[2 * t + 1];
        s0 = (int)va.x; s1 = (int)va.y; s2 = (int)vb.x; s3 = (int)vb.y;
        d0 = (int)vc.x; d1 = (int)vc.y; d2 = (int)vd.x; d3 = (int)vd.y;
    } else {
        const int4* ps = (const int4*)ei32;
        const int4* pd = (const int4*)(ei32 + EE);
        int4 vs = ps[t];
        int4 vd = pd[t];
        s0 = vs.x; s1 = vs.y; s2 = vs.z; s3 = vs.w;
        d0 = vd.x; d1 = vd.y; d2 = vd.z; d3 = vd.w;
    }
    float4 w = ((const float4*)ew)[t];
    int p0 = atomicAdd(&g_cursor[d0], 1);
    int p1 = atomicAdd(&g_cursor[d1], 1);
    int p2 = atomicAdd(&g_cursor[d2], 1);
    int p3 = atomicAdd(&g_cursor[d3], 1);
    g_recs[p0] = make_int2(s0, __float_as_int(w.x));
    g_recs[p1] = make_int2(s1, __float_as_int(w.y));
    g_recs[p2] = make_int2(s2, __float_as_int(w.z));
    g_recs[p3] = make_int2(s3, __float_as_int(w.w));
}

// ---------------------------------------------------------------------------
// Gather: one warp per destination node, no atomics (measured-good, unchanged).
// ---------------------------------------------------------------------------
__global__ __launch_bounds__(256) void gather_kernel(const float4* __restrict__ Xv,
                                                     float4* __restrict__ agg) {
    int warp = (blockIdx.x * blockDim.x + threadIdx.x) >> 5;
    if (warp >= NN) return;
    int lane = threadIdx.x & 31;
    int half = lane >> 4;
    int j    = lane & 15;

    int2 oc   = g_ofscnt[warp];
    int start = oc.x;
    int cnt   = oc.y;

    float4 acc = make_float4(0.f, 0.f, 0.f, 0.f);
    int i = half;
    for (; i + 2 < cnt; i += 4) {
        int2  rec0 = g_recs[start + i];
        int2  rec1 = g_recs[start + i + 2];
        float4 x0  = Xv[rec0.x * 16 + j];
        float4 x1  = Xv[rec1.x * 16 + j];
        float w0   = __int_as_float(rec0.y);
        float w1   = __int_as_float(rec1.y);
        acc.x += x0.x * w0;  acc.y += x0.y * w0;
        acc.z += x0.z * w0;  acc.w += x0.w * w0;
        acc.x += x1.x * w1;  acc.y += x1.y * w1;
        acc.z += x1.z * w1;  acc.w += x1.w * w1;
    }
    if (i < cnt) {
        int2  rec = g_recs[start + i];
        float w   = __int_as_float(rec.y);
        float4 x  = Xv[rec.x * 16 + j];
        acc.x += x.x * w;  acc.y += x.y * w;
        acc.z += x.z * w;  acc.w += x.w * w;
    }
    acc.x += __shfl_down_sync(0xffffffffu, acc.x, 16);
    acc.y += __shfl_down_sync(0xffffffffu, acc.y, 16);
    acc.z += __shfl_down_sync(0xffffffffu, acc.z, 16);
    acc.w += __shfl_down_sync(0xffffffffu, acc.w, 16);
    if (half == 0) agg[warp * 16 + j] = acc;
}

// ---------------------------------------------------------------------------
// Tensor-core dual-GEMM + bias + sigmoid via 3xTF32 mma.m16n8k8 (measured-good).
// ---------------------------------------------------------------------------
__global__ __launch_bounds__(256) void gemm_tf32_kernel(
    const float* __restrict__ A,
    const float* __restrict__ R,
    const float* __restrict__ Wrel,   // [64,64] row-major [out][in]
    const float* __restrict__ Wroot,
    const float* __restrict__ b0, const float* __restrict__ b1,
    const float* __restrict__ b2, const float* __restrict__ b3,
    float* __restrict__ out)
{
    __shared__ uint4 WF[128 * 32];    // 32KB: 2 mats x 64 frags x 32 lanes
    __shared__ float bias_s[64];

    int tid = threadIdx.x;

    if (tid < 64) {
        float b = b0[tid] + b1[tid];
        if (b2 != nullptr) b += b2[tid] + b3[tid];
        bias_s[tid] = b;
    }

    for (int idx = tid; idx < 4096; idx += 256) {
        int lane = idx & 31;
        int frag = idx >> 5;          // 0..127
        int mat  = frag >> 6;
        int rem  = frag & 63;
        int nt   = rem >> 3;
        int ks   = rem & 7;
        int n = nt * 8 + (lane >> 2);
        int k = ks * 8 + (lane & 3);
        const float* W = mat ? Wroot : Wrel;
        unsigned h0, l0, h1, l1;
        tf32_split(W[n * 64 + k],     h0, l0);
        tf32_split(W[n * 64 + k + 4], h1, l1);
        WF[idx] = make_uint4(h0, l0, h1, l1);
    }
    __syncthreads();

    int wid  = tid >> 5;
    int lane = tid & 31;
    int m0   = blockIdx.x * 128 + wid * 16;
    int r0   = m0 + (lane >> 2);
    int r1   = r0 + 8;
    bool v0 = (r0 < NN), v1 = (r1 < NN);

    float acc[8][4];
#pragma unroll
    for (int nt = 0; nt < 8; nt++)
#pragma unroll
        for (int i = 0; i < 4; i++) acc[nt][i] = 0.f;

#pragma unroll
    for (int mat = 0; mat < 2; mat++) {
        const float* S = mat ? R : A;
#pragma unroll
        for (int ks = 0; ks < 8; ks++) {
            int c0 = ks * 8 + (lane & 3);
            float f0 = v0 ? S[r0 * 64 + c0]     : 0.f;
            float f1 = v1 ? S[r1 * 64 + c0]     : 0.f;
            float f2 = v0 ? S[r0 * 64 + c0 + 4] : 0.f;
            float f3 = v1 ? S[r1 * 64 + c0 + 4] : 0.f;
            unsigned ahi[4], alo[4];
            tf32_split(f0, ahi[0], alo[0]);
            tf32_split(f1, ahi[1], alo[1]);
            tf32_split(f2, ahi[2], alo[2]);
            tf32_split(f3, ahi[3], alo[3]);
#pragma unroll
            for (int nt = 0; nt < 8; nt++) {
                uint4 b = WF[((mat << 6) + nt * 8 + ks) * 32 + lane];
                mma8(acc[nt], ahi, b.x, b.z);   // hi*hi
                mma8(acc[nt], ahi, b.y, b.w);   // hi*lo
                mma8(acc[nt], alo, b.x, b.z);   // lo*hi
            }
        }
    }

#pragma unroll
    for (int nt = 0; nt < 8; nt++) {
        int n0 = nt * 8 + (lane & 3) * 2;
        float ba = bias_s[n0], bb = bias_s[n0 + 1];
        if (v0) {
            float2 o;
            o.x = 1.f / (1.f + __expf(-(acc[nt][0] + ba)));
            o.y = 1.f / (1.f + __expf(-(acc[nt][1] + bb)));
            *(float2*)&out[r0 * 64 + n0] = o;
        }
        if (v1) {
            float2 o;
            o.x = 1.f / (1.f + __expf(-(acc[nt][2] + ba)));
            o.y = 1.f / (1.f + __expf(-(acc[nt][3] + bb)));
            *(float2*)&out[r1 * 64 + n0] = o;
        }
    }
}

// ---------------------------------------------------------------------------
extern "C" void kernel_launch(void* const* d_in, const int* in_sizes, int n_in,
                              void* d_out, int out_size)
{
    const float* X      = (const float*)d_in[0];
    const int*   ei     = (const int*)  d_in[1];   // raw; dtype auto-detected
    const float* ew     = (const float*)d_in[2];
    const float* Wrel1  = (const float*)d_in[3];
    const float* brel1  = (const float*)d_in[4];
    const float* Wroot1 = (const float*)d_in[5];
    const float* broot1 = (const float*)d_in[6];
    const float* brel2  = (const float*)d_in[8];
    const float* broot2 = (const float*)d_in[10];
    const float* Wrel3  = (const float*)d_in[11];
    const float* brel3  = (const float*)d_in[12];
    const float* Wroot3 = (const float*)d_in[13];
    const float* broot3 = (const float*)d_in[14];
    float* out = (float*)d_out;

    float *agg, *h;
    cudaGetSymbolAddress((void**)&agg, g_AGG);
    cudaGetSymbolAddress((void**)&h,   g_H);

    // --- CSR build ---
    hist_kernel<<<(EE / 4 + 255) / 256, 256>>>(ei);
    scan_kernel<<<NBLK, SCAN_BS>>>();
    fill_kernel<<<(EE / 4 + 255) / 256, 256>>>(ei, ew);

    // --- pass 1 ---
    gather_kernel<<<(NN * 32 + 255) / 256, 256>>>((const float4*)X, (float4*)agg);
    gemm_tf32_kernel<<<(NN + 127) / 128, 256>>>(
        agg, X, Wrel1, Wroot1, brel1, broot1, brel2, broot2, h);

    // --- pass 2 ---
    gather_kernel<<<(NN * 32 + 255) / 256, 256>>>((const float4*)h, (float4*)agg);
    gemm_tf32_kernel<<<(NN + 127) / 128, 256>>>(
        agg, h, Wrel3, Wroot3, brel3, broot3, nullptr, nullptr, out);
}